// round 3
// baseline (speedup 1.0000x reference)
#include <cuda_runtime.h>
#include <cstdint>

// Masked cumsum along dim 1, single-pass decoupled-lookback scan.
// B=256 rows x N=131072 cols, fp32 x, int32 mask.
//
// Tile = 8192 elems (512 thr x 16 VPT), 16 tiles/row -> 4096 CTAs.
// Each warp owns a contiguous 512-float segment, loaded in 4 perfectly
// coalesced float4/int4 rounds. Scan: lane(4) -> warp(32) -> round-chain(4)
// -> CTA(16 warps) -> cross-tile exclusive prefix via warp-parallel lookback.
// Flags carry {epoch_tag, payload}; epoch comes from a never-reset ticket
// counter so graph replays need no state reset.

#define T_THREADS 512
#define T_NWARPS  16
#define T_VPT     16
#define T_TILE    (T_THREADS * T_VPT)   // 8192
#define T_NCOLS   131072
#define T_TPR     (T_NCOLS / T_TILE)    // 16 tiles per row
#define MAXTILES  8192

__device__ unsigned long long g_ticket;            // never reset; epoch = ticket / gridDim
__device__ unsigned long long g_flags[MAXTILES];   // [31:0]=tag (epoch<<2|state), [63:32]=float payload

__device__ __forceinline__ void st_release_u64(unsigned long long* p, unsigned long long v) {
    asm volatile("st.release.gpu.global.u64 [%0], %1;" :: "l"(p), "l"(v) : "memory");
}
__device__ __forceinline__ unsigned long long ld_acquire_u64(const unsigned long long* p) {
    unsigned long long v;
    asm volatile("ld.acquire.gpu.global.u64 %0, [%1];" : "=l"(v) : "l"(p) : "memory");
    return v;
}

__device__ __forceinline__ float warp_incl_scan(float v, int lane) {
    #pragma unroll
    for (int d = 1; d < 32; d <<= 1) {
        float n = __shfl_up_sync(0xffffffffu, v, d);
        if (lane >= d) v += n;
    }
    return v;
}

__global__ __launch_bounds__(T_THREADS, 2)
void masked_cumsum_lookback(const float* __restrict__ x,
                            const int* __restrict__ mask,
                            float* __restrict__ out) {
    __shared__ float shWarp[T_NWARPS];   // per-warp tile sums
    __shared__ float shWExcl[T_NWARPS];  // per-warp exclusive prefix within tile
    __shared__ float shExcl;             // tile exclusive prefix (cross-tile)
    __shared__ unsigned long long shTicket;

    const int tid  = threadIdx.x;
    const int lane = tid & 31;
    const int warp = tid >> 5;

    // ---- ticket: assigns tiles in scheduling order (lookback deadlock-free) ----
    if (tid == 0) shTicket = atomicAdd(&g_ticket, 1ULL);
    __syncthreads();
    const unsigned long long ticket = shTicket;
    const unsigned totalTiles = gridDim.x;
    const unsigned vt    = (unsigned)(ticket % totalTiles);   // virtual tile id
    const unsigned epoch = (unsigned)(ticket / totalTiles);
    const unsigned tpos  = vt % T_TPR;                        // tile index within row
    const unsigned row   = vt / T_TPR;
    const unsigned tagA  = (epoch << 2) | 1u;                 // aggregate available
    const unsigned tagP  = (epoch << 2) | 2u;                 // inclusive prefix available

    // ---- coalesced loads: warp owns 512 contiguous floats, 4 rounds ----
    const size_t rowF4  = (size_t)row * (T_NCOLS / 4);
    const unsigned tileF4 = tpos * (T_TILE / 4) + warp * 128; // float4 index of warp segment
    const float4* __restrict__ x4 = reinterpret_cast<const float4*>(x) + rowF4 + tileF4;
    const int4*   __restrict__ m4 = reinterpret_cast<const int4*>(mask) + rowF4 + tileF4;
    float4*       __restrict__ o4 = reinterpret_cast<float4*>(out) + rowF4 + tileF4;

    float4 xa0 = x4[lane];
    float4 xa1 = x4[32 + lane];
    float4 xa2 = x4[64 + lane];
    float4 xa3 = x4[96 + lane];
    int4   ma0 = m4[lane];
    int4   ma1 = m4[32 + lane];
    int4   ma2 = m4[64 + lane];
    int4   ma3 = m4[96 + lane];

    // ---- mask + lane-local inclusive scans (4 rounds of 4) ----
    float v[4][4];
    v[0][0] = ma0.x ? xa0.x : 0.f; v[0][1] = ma0.y ? xa0.y : 0.f;
    v[0][2] = ma0.z ? xa0.z : 0.f; v[0][3] = ma0.w ? xa0.w : 0.f;
    v[1][0] = ma1.x ? xa1.x : 0.f; v[1][1] = ma1.y ? xa1.y : 0.f;
    v[1][2] = ma1.z ? xa1.z : 0.f; v[1][3] = ma1.w ? xa1.w : 0.f;
    v[2][0] = ma2.x ? xa2.x : 0.f; v[2][1] = ma2.y ? xa2.y : 0.f;
    v[2][2] = ma2.z ? xa2.z : 0.f; v[2][3] = ma2.w ? xa2.w : 0.f;
    v[3][0] = ma3.x ? xa3.x : 0.f; v[3][1] = ma3.y ? xa3.y : 0.f;
    v[3][2] = ma3.z ? xa3.z : 0.f; v[3][3] = ma3.w ? xa3.w : 0.f;
    #pragma unroll
    for (int b = 0; b < 4; ++b)
        #pragma unroll
        for (int i = 1; i < 4; ++i) v[b][i] += v[b][i - 1];

    // ---- warp scans per round (independent -> ILP), then chain round totals ----
    float lexcl[4], T[4];
    #pragma unroll
    for (int b = 0; b < 4; ++b) {
        float s = v[b][3];
        float incl = warp_incl_scan(s, lane);
        lexcl[b] = incl - s;
        T[b] = __shfl_sync(0xffffffffu, incl, 31);
    }
    float rExcl[4];
    rExcl[0] = 0.f;
    rExcl[1] = T[0];
    rExcl[2] = T[0] + T[1];
    rExcl[3] = T[0] + T[1] + T[2];
    const float warpTotal = rExcl[3] + T[3];

    if (lane == 0) shWarp[warp] = warpTotal;
    __syncthreads();

    // ---- warp 0: CTA scan + publish aggregate + lookback + publish inclusive ----
    if (warp == 0) {
        float w = (lane < T_NWARPS) ? shWarp[lane] : 0.f;
        float incl = warp_incl_scan(w, lane);
        if (lane < T_NWARPS) shWExcl[lane] = incl - w;
        const float aggregate = __shfl_sync(0xffffffffu, incl, T_NWARPS - 1);

        if (tpos == 0) {
            if (lane == 0) {
                unsigned long long word =
                    ((unsigned long long)__float_as_uint(aggregate) << 32) | tagP;
                st_release_u64(&g_flags[vt], word);
                shExcl = 0.f;
            }
        } else {
            // publish aggregate ASAP so successors can proceed
            if (lane == 0) {
                unsigned long long word =
                    ((unsigned long long)__float_as_uint(aggregate) << 32) | tagA;
                st_release_u64(&g_flags[vt], word);
            }
            // warp-parallel lookback
            float excl = 0.f;
            int t = (int)vt - 1;
            const int rowStart = (int)(vt - tpos);
            while (true) {
                int myT = t - lane;
                int state;
                float payload;
                if (myT >= rowStart) {
                    unsigned long long wd = ld_acquire_u64(&g_flags[myT]);
                    unsigned tg = (unsigned)wd;
                    payload = __uint_as_float((unsigned)(wd >> 32));
                    state = (tg == tagP) ? 2 : ((tg == tagA) ? 1 : 0);
                } else { state = 2; payload = 0.f; }
                unsigned preM = __ballot_sync(0xffffffffu, state == 2);
                unsigned invM = __ballot_sync(0xffffffffu, state == 0);
                if (preM) {
                    int fp = __ffs(preM) - 1;
                    unsigned below = fp ? (invM & ((1u << fp) - 1u)) : 0u;
                    if (!below) {
                        float c = (lane <= fp) ? payload : 0.f;
                        #pragma unroll
                        for (int d = 16; d; d >>= 1) c += __shfl_xor_sync(0xffffffffu, c, d);
                        excl += c;
                        break;
                    }
                } else if (!invM) {
                    float c = payload;
                    #pragma unroll
                    for (int d = 16; d; d >>= 1) c += __shfl_xor_sync(0xffffffffu, c, d);
                    excl += c;
                    t -= 32;
                }
                // else: spin-retry same window
            }
            if (lane == 0) {
                unsigned long long word =
                    ((unsigned long long)__float_as_uint(excl + aggregate) << 32) | tagP;
                st_release_u64(&g_flags[vt], word);
                shExcl = excl;
            }
        }
    }
    __syncthreads();

    // ---- add bases, coalesced store ----
    const float base0 = shExcl + shWExcl[warp];
    #pragma unroll
    for (int b = 0; b < 4; ++b) {
        const float base = base0 + rExcl[b] + lexcl[b];
        float4 o;
        o.x = v[b][0] + base;
        o.y = v[b][1] + base;
        o.z = v[b][2] + base;
        o.w = v[b][3] + base;
        o4[b * 32 + lane] = o;
    }
}

extern "C" void kernel_launch(void* const* d_in, const int* in_sizes, int n_in,
                              void* d_out, int out_size) {
    const float* x    = (const float*)d_in[0];
    const int*   mask = (const int*)d_in[1];
    float*       out  = (float*)d_out;
    const int rows = out_size / T_NCOLS;            // 256
    const int tiles = rows * T_TPR;                 // 4096
    masked_cumsum_lookback<<<tiles, T_THREADS>>>(x, mask, out);
}

// round 4
// speedup vs baseline: 1.5182x; 1.5182x over previous
#include <cuda_runtime.h>
#include <cstdint>

// Masked cumsum along dim 1: out[b,:] = cumsum(where(mask, x, 0))
// B=256 rows, N=131072 cols, fp32 x, int32 mask.
//
// R2 structure (one persistent CTA per row, serial carry over 32 chunks of
// 4096) with the coalescing fix: each warp owns a contiguous 256-float
// segment per chunk, loaded as 2 rounds of lane-consecutive float4/int4 so
// every LDG/STG.128 touches exactly 4 cache lines (R2's per-thread-contiguous
// layout touched 8). Scan: lane(4) -> warp-per-round(32) -> round chain(2)
// -> CTA(16 warps) -> running carry. One-chunk-ahead register prefetch;
// streaming cache hints since every byte is touched once.

#define CS_THREADS 512
#define CS_NWARPS  16
#define CS_CHUNK   4096                   // 512 thr * 8 elems
#define CS_NCOLS   131072
#define CS_ITERS   (CS_NCOLS / CS_CHUNK)  // 32

__device__ __forceinline__ float warp_incl_scan(float v, int lane) {
    #pragma unroll
    for (int d = 1; d < 32; d <<= 1) {
        float n = __shfl_up_sync(0xffffffffu, v, d);
        if (lane >= d) v += n;
    }
    return v;
}

__global__ __launch_bounds__(CS_THREADS, 2)
void masked_cumsum_kernel(const float* __restrict__ x,
                          const int* __restrict__ mask,
                          float* __restrict__ out) {
    __shared__ float sh[2][CS_NWARPS + 1];  // [buf][0..15]=warp excl prefix, [16]=chunk total

    const int row = blockIdx.x;
    const size_t roff4 = (size_t)row * (CS_NCOLS / 4);
    const float4* __restrict__ x4 = reinterpret_cast<const float4*>(x) + roff4;
    const int4*   __restrict__ m4 = reinterpret_cast<const int4*>(mask) + roff4;
    float4*       __restrict__ o4 = reinterpret_cast<float4*>(out) + roff4;

    const int tid  = threadIdx.x;
    const int lane = tid & 31;
    const int warp = tid >> 5;
    // Warp w owns floats [w*256, w*256+256) of each chunk:
    // round r (0,1), lane l -> float4 index w*64 + r*32 + l  (perfectly coalesced)
    const int wbase = warp * 64 + lane;

    float carry = 0.0f;

    // Prefetch chunk 0
    float4 pa0 = __ldcs(&x4[wbase]);
    float4 pa1 = __ldcs(&x4[wbase + 32]);
    int4   pm0 = __ldcs(&m4[wbase]);
    int4   pm1 = __ldcs(&m4[wbase + 32]);

    for (int it = 0; it < CS_ITERS; ++it) {
        const float4 xa0 = pa0, xa1 = pa1;
        const int4   ma0 = pm0, ma1 = pm1;
        // Issue next chunk's loads immediately; consumed next iteration.
        if (it + 1 < CS_ITERS) {
            const int nb = (it + 1) * (CS_CHUNK / 4) + wbase;
            pa0 = __ldcs(&x4[nb]);
            pa1 = __ldcs(&x4[nb + 32]);
            pm0 = __ldcs(&m4[nb]);
            pm1 = __ldcs(&m4[nb + 32]);
        }

        // Apply mask (each int32 is 0 or 1)
        float v[2][4];
        v[0][0] = ma0.x ? xa0.x : 0.f; v[0][1] = ma0.y ? xa0.y : 0.f;
        v[0][2] = ma0.z ? xa0.z : 0.f; v[0][3] = ma0.w ? xa0.w : 0.f;
        v[1][0] = ma1.x ? xa1.x : 0.f; v[1][1] = ma1.y ? xa1.y : 0.f;
        v[1][2] = ma1.z ? xa1.z : 0.f; v[1][3] = ma1.w ? xa1.w : 0.f;

        // Lane-local inclusive scans (2 independent rounds -> ILP)
        #pragma unroll
        for (int b = 0; b < 2; ++b)
            #pragma unroll
            for (int i = 1; i < 4; ++i) v[b][i] += v[b][i - 1];

        // Warp scan per round, then chain the two round totals
        float lexcl[2], T[2];
        #pragma unroll
        for (int b = 0; b < 2; ++b) {
            const float s = v[b][3];
            const float incl = warp_incl_scan(s, lane);
            lexcl[b] = incl - s;
            T[b] = __shfl_sync(0xffffffffu, incl, 31);
        }
        const float warpTotal = T[0] + T[1];

        const int buf = it & 1;
        if (lane == 0) sh[buf][warp] = warpTotal;
        __syncthreads();

        // Warp 0 scans the 16 warp totals
        if (warp == 0) {
            const float w = (lane < CS_NWARPS) ? sh[buf][lane] : 0.f;
            const float ws = warp_incl_scan(w, lane);
            if (lane < CS_NWARPS)      sh[buf][lane]      = ws - w;  // exclusive warp prefix
            if (lane == CS_NWARPS - 1) sh[buf][CS_NWARPS] = ws;      // chunk total
        }
        __syncthreads();

        const float base0 = carry + sh[buf][warp];
        carry += sh[buf][CS_NWARPS];

        const float baseA = base0 + lexcl[0];
        const float baseB = base0 + T[0] + lexcl[1];
        const int ob = it * (CS_CHUNK / 4) + wbase;
        float4 oa, obv;
        oa.x  = v[0][0] + baseA; oa.y  = v[0][1] + baseA;
        oa.z  = v[0][2] + baseA; oa.w  = v[0][3] + baseA;
        obv.x = v[1][0] + baseB; obv.y = v[1][1] + baseB;
        obv.z = v[1][2] + baseB; obv.w = v[1][3] + baseB;
        __stcs(&o4[ob],      oa);
        __stcs(&o4[ob + 32], obv);
        // No trailing barrier: next iteration uses the other smem buffer.
    }
}

extern "C" void kernel_launch(void* const* d_in, const int* in_sizes, int n_in,
                              void* d_out, int out_size) {
    const float* x    = (const float*)d_in[0];
    const int*   mask = (const int*)d_in[1];
    float*       out  = (float*)d_out;
    const int rows = out_size / CS_NCOLS;   // 256
    masked_cumsum_kernel<<<rows, CS_THREADS>>>(x, mask, out);
}

// round 5
// speedup vs baseline: 1.7237x; 1.1354x over previous
#include <cuda_runtime.h>
#include <cstdint>

// Masked cumsum along dim 1: out[b,:] = cumsum(where(mask, x, 0))
// B=256 rows, N=131072 cols, fp32 x, int32 mask.
//
// One persistent CTA per row, serial carry over 32 chunks of 4096. Each warp
// owns a contiguous 256-float segment per chunk (2 rounds of lane-consecutive
// float4/int4 -> every LDG/STG.128 is a perfect 4-line access). One-chunk-
// ahead register prefetch; streaming cache hints.
//
// R5 change: ONE barrier per iteration. Instead of bar -> warp0 scans warp
// totals -> bar -> all read, every warp redundantly loads all 16 warp totals
// from smem (broadcast, conflict-free) after a single barrier and scans them
// itself (4 shfl steps), deriving its own exclusive prefix + chunk total.
// Removes one barrier and the 15-warps-idle warp0 serialization per chunk.

#define CS_THREADS 512
#define CS_NWARPS  16
#define CS_CHUNK   4096                   // 512 thr * 8 elems
#define CS_NCOLS   131072
#define CS_ITERS   (CS_NCOLS / CS_CHUNK)  // 32

__device__ __forceinline__ float warp_incl_scan(float v, int lane) {
    #pragma unroll
    for (int d = 1; d < 32; d <<= 1) {
        float n = __shfl_up_sync(0xffffffffu, v, d);
        if (lane >= d) v += n;
    }
    return v;
}

__global__ __launch_bounds__(CS_THREADS, 2)
void masked_cumsum_kernel(const float* __restrict__ x,
                          const int* __restrict__ mask,
                          float* __restrict__ out) {
    __shared__ float sh[2][CS_NWARPS];   // [buf][w] = warp w's chunk total

    const int row = blockIdx.x;
    const size_t roff4 = (size_t)row * (CS_NCOLS / 4);
    const float4* __restrict__ x4 = reinterpret_cast<const float4*>(x) + roff4;
    const int4*   __restrict__ m4 = reinterpret_cast<const int4*>(mask) + roff4;
    float4*       __restrict__ o4 = reinterpret_cast<float4*>(out) + roff4;

    const int tid  = threadIdx.x;
    const int lane = tid & 31;
    const int warp = tid >> 5;
    // Warp w owns floats [w*256, w*256+256) of each chunk:
    // round r (0,1), lane l -> float4 index w*64 + r*32 + l (perfectly coalesced)
    const int wbase = warp * 64 + lane;

    float carry = 0.0f;

    // Prefetch chunk 0
    float4 pa0 = __ldcs(&x4[wbase]);
    float4 pa1 = __ldcs(&x4[wbase + 32]);
    int4   pm0 = __ldcs(&m4[wbase]);
    int4   pm1 = __ldcs(&m4[wbase + 32]);

    for (int it = 0; it < CS_ITERS; ++it) {
        const float4 xa0 = pa0, xa1 = pa1;
        const int4   ma0 = pm0, ma1 = pm1;
        // Issue next chunk's loads immediately; consumed next iteration.
        if (it + 1 < CS_ITERS) {
            const int nb = (it + 1) * (CS_CHUNK / 4) + wbase;
            pa0 = __ldcs(&x4[nb]);
            pa1 = __ldcs(&x4[nb + 32]);
            pm0 = __ldcs(&m4[nb]);
            pm1 = __ldcs(&m4[nb + 32]);
        }

        // Apply mask (each int32 is 0 or 1)
        float v[2][4];
        v[0][0] = ma0.x ? xa0.x : 0.f; v[0][1] = ma0.y ? xa0.y : 0.f;
        v[0][2] = ma0.z ? xa0.z : 0.f; v[0][3] = ma0.w ? xa0.w : 0.f;
        v[1][0] = ma1.x ? xa1.x : 0.f; v[1][1] = ma1.y ? xa1.y : 0.f;
        v[1][2] = ma1.z ? xa1.z : 0.f; v[1][3] = ma1.w ? xa1.w : 0.f;

        // Lane-local inclusive scans (2 independent rounds -> ILP)
        #pragma unroll
        for (int b = 0; b < 2; ++b)
            #pragma unroll
            for (int i = 1; i < 4; ++i) v[b][i] += v[b][i - 1];

        // Warp scan per round (two independent shfl chains), chain round totals
        float lexcl[2], T[2];
        #pragma unroll
        for (int b = 0; b < 2; ++b) {
            const float s = v[b][3];
            const float incl = warp_incl_scan(s, lane);
            lexcl[b] = incl - s;
            T[b] = __shfl_sync(0xffffffffu, incl, 31);
        }
        const float warpTotal = T[0] + T[1];

        const int buf = it & 1;
        if (lane == 0) sh[buf][warp] = warpTotal;
        __syncthreads();

        // Every warp redundantly scans the 16 warp totals (smem broadcast read,
        // 4-step shfl prefix over lanes 0..15). No second barrier, no warp0 wait.
        float w = (lane < CS_NWARPS) ? sh[buf][lane] : 0.f;
        float wincl = w;
        #pragma unroll
        for (int d = 1; d < CS_NWARPS; d <<= 1) {
            float n = __shfl_up_sync(0xffffffffu, wincl, d);
            if (lane >= d) wincl += n;
        }
        const float wexcl      = __shfl_sync(0xffffffffu, wincl, warp) -
                                 __shfl_sync(0xffffffffu, w,     warp);
        const float chunkTotal = __shfl_sync(0xffffffffu, wincl, CS_NWARPS - 1);

        const float base0 = carry + wexcl;
        carry += chunkTotal;

        const float baseA = base0 + lexcl[0];
        const float baseB = base0 + T[0] + lexcl[1];
        const int ob = it * (CS_CHUNK / 4) + wbase;
        float4 oa, obv;
        oa.x  = v[0][0] + baseA; oa.y  = v[0][1] + baseA;
        oa.z  = v[0][2] + baseA; oa.w  = v[0][3] + baseA;
        obv.x = v[1][0] + baseB; obv.y = v[1][1] + baseB;
        obv.z = v[1][2] + baseB; obv.w = v[1][3] + baseB;
        __stcs(&o4[ob],      oa);
        __stcs(&o4[ob + 32], obv);
        // No trailing barrier: iter i+2's STS to this buf is fenced by iter i+1's bar.
    }
}

extern "C" void kernel_launch(void* const* d_in, const int* in_sizes, int n_in,
                              void* d_out, int out_size) {
    const float* x    = (const float*)d_in[0];
    const int*   mask = (const int*)d_in[1];
    float*       out  = (float*)d_out;
    const int rows = out_size / CS_NCOLS;   // 256
    masked_cumsum_kernel<<<rows, CS_THREADS>>>(x, mask, out);
}